// round 15
// baseline (speedup 1.0000x reference)
#include <cuda_runtime.h>

// Problem constants (fixed by setup_inputs)
#define NB        64
#define SD        52
#define CELLS     (SD * SD)        // 2704
#define CH        255
#define NCELLS    (NB * CELLS)     // 173056 (one warp per cell)
#define EPSF      1e-6f
#define IOU_T     0.7f
#define SCALE_IDX 2

__device__ __forceinline__ float warp_sum(float v) {
    #pragma unroll
    for (int o = 16; o > 0; o >>= 1) v += __shfl_xor_sync(0xffffffffu, v, o);
    return v;
}

#define SEL3(i, a, b, c) ((i) == 0 ? (a) : ((i) == 1 ? (b) : (c)))

__global__ __launch_bounds__(128, 7) void yolo_loss_kernel(
    const float* __restrict__ yhat,
    const float* __restrict__ ytru,
    const float* __restrict__ anchors,
    float* __restrict__ out)
{
    const int cell = blockIdx.x * 4 + (threadIdx.x >> 5);  // 0..173055
    const int lane = threadIdx.x & 31;
    const int n  = cell / CELLS;
    const int ci = cell - n * CELLS;
    const int gi = ci / SD;
    const int gj = ci - gi * SD;

    const float* Hb = yhat + (size_t)cell * CH;
    const float* Yb = ytru + (size_t)cell * CH;

    // ---- 1) Class windows FIRST: 18 coalesced warp-LDGs (nL<=2 each),
    // independent of everything; in flight through the whole IOU phase.
    float Hc[3][3], Yc[3][3];
    #pragma unroll
    for (int b = 0; b < 3; b++) {
        const float* h = Hb + b * 85 + 5;
        const float* y = Yb + b * 85 + 5;
        Hc[b][0] = __ldg(h + lane);
        Yc[b][0] = __ldg(y + lane);
        Hc[b][1] = __ldg(h + lane + 32);
        Yc[b][1] = __ldg(y + lane + 32);
        Hc[b][2] = (lane < 16) ? __ldg(h + lane + 64) : 0.0f;
        Yc[b][2] = (lane < 16) ? __ldg(y + lane + 64) : 0.0f;
    }

    // ---- 2) Box fields: 30 broadcast LDGs (1 sector each).
    const float invS = 1.0f / (float)SD;
    const float fj = (float)gj, fi = (float)gi;

    float hcx[3], hcy[3], hw[3], hh[3], hcf[3];
    float ycx[3], ycy[3], yw[3], yh[3], ycf[3];
    #pragma unroll
    for (int b = 0; b < 3; b++) {
        const float* hb = Hb + b * 85;
        const float* yb = Yb + b * 85;
        hcx[b] = (__ldg(hb + 0) + fj) * invS;
        hcy[b] = (__ldg(hb + 1) + fi) * invS;
        hw[b]  =  __ldg(hb + 2);
        hh[b]  =  __ldg(hb + 3);
        hcf[b] =  __ldg(hb + 4);
        ycx[b] = (__ldg(yb + 0) + fj) * invS;
        ycy[b] = (__ldg(yb + 1) + fi) * invS;
        yw[b]  =  __ldg(yb + 2);
        yh[b]  =  __ldg(yb + 3);
        ycf[b] =  __ldg(yb + 4);
    }

    // ---- 3) IOU 3x3 (warp-redundant, register-only).
    int   idx_t[3];
    float best_t[3] = {-1.0f, -1.0f, -1.0f};
    float noobj_acc = 0.0f;
    #pragma unroll
    for (int pb = 0; pb < 3; pb++) {
        float px1 = hcx[pb] - 0.5f * hw[pb], px2 = hcx[pb] + 0.5f * hw[pb];
        float py1 = hcy[pb] - 0.5f * hh[pb], py2 = hcy[pb] + 0.5f * hh[pb];
        float pa  = hw[pb] * hh[pb];
        float m = -1.0f;
        #pragma unroll
        for (int tb = 0; tb < 3; tb++) {
            float wi = fmaxf(fminf(px2, ycx[tb] + 0.5f * yw[tb]) -
                             fmaxf(px1, ycx[tb] - 0.5f * yw[tb]), 0.0f);
            float hi = fmaxf(fminf(py2, ycy[tb] + 0.5f * yh[tb]) -
                             fmaxf(py1, ycy[tb] - 0.5f * yh[tb]), 0.0f);
            float inter = wi * hi;
            float uni = pa + yw[tb] * yh[tb] - inter;
            float iou = inter / (uni + EPSF);
            m = fmaxf(m, iou);
            if (iou > best_t[tb]) { best_t[tb] = iou; idx_t[tb] = pb; }
        }
        if (m < IOU_T) noobj_acc += hcf[pb] * hcf[pb];   // NO_OBJ_V3 target=0
    }

    const float ho0 = (ycf[0] > 0.0f) ? 1.0f : 0.0f;
    const float ho1 = (ycf[1] > 0.0f) ? 1.0f : 0.0f;
    const float ho2 = (ycf[2] > 0.0f) ? 1.0f : 0.0f;

    // ---- 4) Coord/obj losses (warp-redundant; warp-uniform results).
    float coord_acc = 0.0f, obj_acc = 0.0f;
    {
        const float* anc = anchors + SCALE_IDX * 6;
        #pragma unroll
        for (int tb = 0; tb < 3; tb++) {
            const int pb = idx_t[tb];
            float ho = (tb == 0) ? ho0 : (tb == 1) ? ho1 : ho2;
            float cxp = SEL3(pb, hcx[0], hcx[1], hcx[2]);
            float cyp = SEL3(pb, hcy[0], hcy[1], hcy[2]);
            float bwp = SEL3(pb, hw[0],  hw[1],  hw[2]);
            float bhp = SEL3(pb, hh[0],  hh[1],  hh[2]);
            float cfp = SEL3(pb, hcf[0], hcf[1], hcf[2]);
            float aw_p = __ldg(anc + pb * 2), ah_p = __ldg(anc + pb * 2 + 1);
            float aw_t = __ldg(anc + tb * 2), ah_t = __ldg(anc + tb * 2 + 1);
            float dx = (cxp - ycx[tb]) * (float)SD;
            float dy = (cyp - ycy[tb]) * (float)SD;
            float dlw = __logf(bwp / aw_p + EPSF) - __logf(yw[tb] / aw_t + EPSF);
            float dlh = __logf(bhp / ah_p + EPSF) - __logf(yh[tb] / ah_t + EPSF);
            float c = dx * dx + dy * dy + dlw * dlw + dlh * dlh;
            coord_acc += c * ho * (2.0f - yw[tb] * yh[tb]);   // SCALE_COORD
            float dc = cfp - ycf[tb];
            obj_acc += dc * dc * ho;
        }
    }

    // ---- 5) Class loss: register selects on compile-time-indexed arrays.
    float cls_acc = 0.0f;
    #pragma unroll
    for (int tb = 0; tb < 3; tb++) {
        const int pb = idx_t[tb];
        float ho = (tb == 0) ? ho0 : (tb == 1) ? ho1 : ho2;
        float s = 0.0f;
        #pragma unroll
        for (int k = 0; k < 3; k++) {
            float hv = SEL3(pb, Hc[0][k], Hc[1][k], Hc[2][k]);
            float d = hv - Yc[tb][k];
            s += d * d;                    // lanes>=16, k=2: 0-0=0
        }
        cls_acc += s * ho;
    }
    cls_acc = warp_sum(cls_acc);

    // ---- 6) Commit (coord/obj/noobj warp-uniform).
    if (lane == 0) {
        // layout: coord[0:64) class[64:128) noobj[128:192) obj[192:256) prior
        atomicAdd(out + 0 * NB + n, coord_acc);
        atomicAdd(out + 1 * NB + n, cls_acc);
        atomicAdd(out + 2 * NB + n, noobj_acc);
        atomicAdd(out + 3 * NB + n, obj_acc);
    }
}

extern "C" void kernel_launch(void* const* d_in, const int* in_sizes, int n_in,
                              void* d_out, int out_size) {
    const float* yhat    = (const float*)d_in[0];
    const float* y       = (const float*)d_in[1];
    const float* anchors = (const float*)d_in[2];
    float* out = (float*)d_out;

    cudaMemsetAsync(out, 0, (size_t)out_size * sizeof(float));
    yolo_loss_kernel<<<NCELLS / 4, 128>>>(yhat, y, anchors, out);  // 43264 blocks
}

// round 17
// speedup vs baseline: 3.9403x; 3.9403x over previous
#include <cuda_runtime.h>

// Problem constants (fixed by setup_inputs)
#define NB        64
#define SD        52
#define CELLS     (SD * SD)             // 2704
#define CH        255
#define QCELLS    4                     // cells per warp
#define NQUADS    (NB * CELLS / QCELLS) // 43264
#define QPI       (CELLS / QCELLS)      // 676 quads per image
#define EPSF      1e-6f
#define IOU_T     0.7f
#define SCALE_IDX 2

__device__ __forceinline__ float warp_sum(float v) {
    #pragma unroll
    for (int o = 16; o > 0; o >>= 1) v += __shfl_down_sync(0xffffffffu, v, o);
    return v;
}

__global__ __launch_bounds__(128, 8) void yolo_loss_kernel(
    const float* __restrict__ yhat,
    const float* __restrict__ ytru,
    const float* __restrict__ anchors,
    float* __restrict__ out)
{
    const int wl   = threadIdx.x >> 5;
    const int lane = threadIdx.x & 31;
    const int quad = blockIdx.x * 4 + wl;     // 0..43263 (grid exact)
    const int n    = quad / QPI;              // image
    const int c0   = (quad % QPI) * QCELLS;

    const int g   = lane >> 3;                // cell within quad (0..3)
    const int sub = lane & 7;                 // lane within cell group
    const int cellIdx = c0 + g;
    const int gi = cellIdx / SD;
    const int gj = cellIdx % SD;

    const size_t base = ((size_t)n * CELLS + cellIdx) * CH;
    const float* Hb = yhat + base;
    const float* Yb = ytru + base;

    // ---- Box fields, cooperative: ONE warp-LDG per record fetches the 5
    // fields of that record for ALL 4 cells (lanes load base+sub; sub<8<85
    // always in-bounds), then intra-group shuffles redistribute.
    float rv[6];
    #pragma unroll
    for (int b = 0; b < 3; b++) {
        rv[b]     = __ldg(Hb + b * 85 + sub);
        rv[3 + b] = __ldg(Yb + b * 85 + sub);
    }
    const int gbase = lane & 24;              // first lane of this 8-lane group

    const float invS = 1.0f / (float)SD;
    const float fj = (float)gj, fi = (float)gi;

    float hcx[3], hcy[3], hw[3], hh[3], hcf[3];
    float ycx[3], ycy[3], yw[3], yh[3], ycf[3];
    #pragma unroll
    for (int b = 0; b < 3; b++) {
        hcx[b] = (__shfl_sync(0xffffffffu, rv[b], gbase + 0) + fj) * invS;
        hcy[b] = (__shfl_sync(0xffffffffu, rv[b], gbase + 1) + fi) * invS;
        hw[b]  =  __shfl_sync(0xffffffffu, rv[b], gbase + 2);
        hh[b]  =  __shfl_sync(0xffffffffu, rv[b], gbase + 3);
        hcf[b] =  __shfl_sync(0xffffffffu, rv[b], gbase + 4);
        ycx[b] = (__shfl_sync(0xffffffffu, rv[3 + b], gbase + 0) + fj) * invS;
        ycy[b] = (__shfl_sync(0xffffffffu, rv[3 + b], gbase + 1) + fi) * invS;
        yw[b]  =  __shfl_sync(0xffffffffu, rv[3 + b], gbase + 2);
        yh[b]  =  __shfl_sync(0xffffffffu, rv[3 + b], gbase + 3);
        ycf[b] =  __shfl_sync(0xffffffffu, rv[3 + b], gbase + 4);
    }

    // ---- IOU 3x3: per-pb max -> noobj term; per-tb argmax -> responsible box.
    int   idx_t[3];
    float best_t[3] = {-1.0f, -1.0f, -1.0f};
    float noobj_acc = 0.0f;
    #pragma unroll
    for (int pb = 0; pb < 3; pb++) {
        float px1 = hcx[pb] - 0.5f * hw[pb], px2 = hcx[pb] + 0.5f * hw[pb];
        float py1 = hcy[pb] - 0.5f * hh[pb], py2 = hcy[pb] + 0.5f * hh[pb];
        float pa  = hw[pb] * hh[pb];
        float m = -1.0f;
        #pragma unroll
        for (int tb = 0; tb < 3; tb++) {
            float wi = fmaxf(fminf(px2, ycx[tb] + 0.5f * yw[tb]) -
                             fmaxf(px1, ycx[tb] - 0.5f * yw[tb]), 0.0f);
            float hi = fmaxf(fminf(py2, ycy[tb] + 0.5f * yh[tb]) -
                             fmaxf(py1, ycy[tb] - 0.5f * yh[tb]), 0.0f);
            float inter = wi * hi;
            float uni = pa + yw[tb] * yh[tb] - inter;
            float iou = inter / (uni + EPSF);
            m = fmaxf(m, iou);
            if (iou > best_t[tb]) { best_t[tb] = iou; idx_t[tb] = pb; }
        }
        if (sub == 0 && m < IOU_T) noobj_acc += hcf[pb] * hcf[pb];  // NO_OBJ_V3
    }

    // ---- Scalar losses (one lane per cell).
    float coord_acc = 0.0f, obj_acc = 0.0f;
    if (sub == 0) {
        const float* anc = anchors + SCALE_IDX * 6;
        #pragma unroll
        for (int tb = 0; tb < 3; tb++) {
            int pb = idx_t[tb];
            float ho = (ycf[tb] > 0.0f) ? 1.0f : 0.0f;
            float aw_p = __ldg(anc + pb * 2), ah_p = __ldg(anc + pb * 2 + 1);
            float aw_t = __ldg(anc + tb * 2), ah_t = __ldg(anc + tb * 2 + 1);
            float dx = (hcx[pb] - ycx[tb]) * (float)SD;   // == x_hat - x_true
            float dy = (hcy[pb] - ycy[tb]) * (float)SD;
            float dlw = __logf(hw[pb] / aw_p + EPSF) - __logf(yw[tb] / aw_t + EPSF);
            float dlh = __logf(hh[pb] / ah_p + EPSF) - __logf(yh[tb] / ah_t + EPSF);
            float c = dx * dx + dy * dy + dlw * dlw + dlh * dlh;
            coord_acc += c * ho * (2.0f - yw[tb] * yh[tb]);   // SCALE_COORD
            float dc = hcf[pb] - ycf[tb];
            obj_acc += dc * dc * ho;
        }
    }

    // ---- Class loss: stream straight from global, 32B sectors per group.
    float cls_acc = 0.0f;
    #pragma unroll
    for (int tb = 0; tb < 3; tb++) {
        int pb = idx_t[tb];
        float ho = (ycf[tb] > 0.0f) ? 1.0f : 0.0f;
        const float* Hc = Hb + pb * 85 + 5;
        const float* Yc = Yb + tb * 85 + 5;
        float s = 0.0f;
        #pragma unroll
        for (int c = sub; c < 80; c += 8) {
            float d = __ldg(Hc + c) - __ldg(Yc + c);
            s += d * d;
        }
        cls_acc += s * ho;
    }

    // ---- Warp reduction (all 4 cells share image n) + atomics.
    coord_acc = warp_sum(coord_acc);
    cls_acc   = warp_sum(cls_acc);
    noobj_acc = warp_sum(noobj_acc);
    obj_acc   = warp_sum(obj_acc);

    if (lane == 0) {
        // layout: coord[0:64) class[64:128) noobj[128:192) obj[192:256) prior
        atomicAdd(out + 0 * NB + n, coord_acc);
        atomicAdd(out + 1 * NB + n, cls_acc);
        atomicAdd(out + 2 * NB + n, noobj_acc);
        atomicAdd(out + 3 * NB + n, obj_acc);
    }
}

extern "C" void kernel_launch(void* const* d_in, const int* in_sizes, int n_in,
                              void* d_out, int out_size) {
    const float* yhat    = (const float*)d_in[0];
    const float* y       = (const float*)d_in[1];
    const float* anchors = (const float*)d_in[2];
    float* out = (float*)d_out;

    cudaMemsetAsync(out, 0, (size_t)out_size * sizeof(float));
    yolo_loss_kernel<<<NQUADS / 4, 128>>>(yhat, y, anchors, out);  // 10816 blocks
}